// round 9
// baseline (speedup 1.0000x reference)
#include <cuda_runtime.h>

// h_t = alpha_t * h_{t-1} + x_t over axis 1 of float32 [4, 8192, 1024].
// Persistent design (R6 skeleton): one block per (batch, 32-wide d-tile)
// chain = 128 blocks. Each block scans S=8192 in 32 chunks of 256 steps with
// register double-buffered prefetch. R9: adds warp-granular prefetch.global.L2
// of chunk k+2 (1 instruction/warp/chunk covers all 32 cache lines of the
// warp's k+2 slab) to keep the DRAM queue 2 chunk-bodies deep and close the
// per-body burst gap.

#define B_      4
#define S_      8192
#define D_      1024
#define R_      16                    // s-steps per thread per chunk
#define SUBS_   16                    // warps per block
#define TPB_    512
#define DTILE_  32                    // d-lanes per block
#define CHUNK_  (R_ * SUBS_)          // 256 s-steps per chunk
#define ITERS_  (S_ / CHUNK_)         // 32 chunks per chain
#define LG_     (B_ * (D_ / DTILE_))  // 128 chains = 128 blocks

// One chunk body. CUR/NXT are compile-time buffer indices (ping-pong).
// Order: L2-prefetch chunk K+2 (fire-and-forget), demand-load chunk K+1 into
// registers, local scan of K, barrier, fold, stores. All memory issue happens
// before the barrier so DRAM streams through the serial section.
#define BODY(CUR, NXT, K)                                                     \
    {                                                                         \
        if ((K) + 2 < ITERS_) {                                               \
            /* one prefetch instr per warp: lanes 0-15 cover the 16 A-rows, */\
            /* lanes 16-31 the 16 X-rows of this warp's chunk-(K+2) slab.   */\
            const float* pfa = (lane < 16) ? alpha : x;                       \
            const float* pf  = pfa + (base + (size_t)2 * CHUNK_ * D_          \
                                      + (size_t)(lane & 15) * D_              \
                                      - (size_t)lane);                        \
            asm volatile("prefetch.global.L2 [%0];" :: "l"(pf));              \
        }                                                                     \
        const size_t nbase = base + (size_t)CHUNK_ * D_;                      \
        if ((K) + 1 < ITERS_) {                                               \
            _Pragma("unroll")                                                 \
            for (int r = 0; r < R_; r++)                                      \
                A[NXT][r] = __ldcs(alpha + nbase + (size_t)r * D_);           \
            _Pragma("unroll")                                                 \
            for (int r = 0; r < R_; r++)                                      \
                X[NXT][r] = __ldcs(x + nbase + (size_t)r * D_);               \
        }                                                                     \
        float P = 1.0f, L = 0.0f;                                             \
        _Pragma("unroll")                                                     \
        for (int r = 0; r < R_; r++) {                                        \
            L = fmaf(A[CUR][r], L, X[CUR][r]);                                \
            P = P * A[CUR][r];                                                \
            A[CUR][r] = P;   /* per-step cumprod  */                          \
            X[CUR][r] = L;   /* per-step local scan */                        \
        }                                                                     \
        sp[CUR][w][lane] = P;                                                 \
        sl[CUR][w][lane] = L;                                                 \
        __syncthreads();                                                      \
        /* every warp folds all 16 aggregates: h0 = prefix before own warp, */\
        /* acc = full fold -> next chunk's carry (identical in all warps).  */\
        float acc = cin, h0 = cin;                                            \
        _Pragma("unroll")                                                     \
        for (int w2 = 0; w2 < SUBS_; w2++) {                                  \
            if (w2 == w) h0 = acc;                                            \
            acc = fmaf(sp[CUR][w2][lane], acc, sl[CUR][w2][lane]);            \
        }                                                                     \
        cin = acc;                                                            \
        _Pragma("unroll")                                                     \
        for (int r = 0; r < R_; r++)                                          \
            __stcs(out + base + (size_t)r * D_, fmaf(A[CUR][r], h0, X[CUR][r]));\
        base = nbase;                                                         \
    }

__global__ __launch_bounds__(TPB_, 1) void scan_kernel(const float* __restrict__ x,
                                                       const float* __restrict__ alpha,
                                                       float* __restrict__ out) {
    // Double-buffered per-warp aggregates: one __syncthreads per chunk is
    // race-free (sync at k+1 separates read(k) from write(k+2), same buffer).
    __shared__ float sp[2][SUBS_][DTILE_];
    __shared__ float sl[2][SUBS_][DTILE_];

    const int lane = threadIdx.x & 31;
    const int w    = threadIdx.x >> 5;    // warp = s-subchunk within chunk
    const int lg   = blockIdx.x;          // chain: b * 32 + dtile
    const int b    = lg >> 5;
    const int dt   = lg & 31;
    const int d    = dt * DTILE_ + lane;

    size_t base = ((size_t)b * S_ + (size_t)w * R_) * (size_t)D_ + d;

    float A[2][R_], X[2][R_];
    float cin = 0.0f;

    // Prefetch chunk 1 lines, then preload chunk 0.
    {
        const float* pfa = (lane < 16) ? alpha : x;
        const float* pf  = pfa + (base + (size_t)CHUNK_ * D_
                                  + (size_t)(lane & 15) * D_ - (size_t)lane);
        asm volatile("prefetch.global.L2 [%0];" :: "l"(pf));
    }
#pragma unroll
    for (int r = 0; r < R_; r++) A[0][r] = __ldcs(alpha + base + (size_t)r * D_);
#pragma unroll
    for (int r = 0; r < R_; r++) X[0][r] = __ldcs(x + base + (size_t)r * D_);

#pragma unroll 1
    for (int k = 0; k < ITERS_; k += 2) {
        BODY(0, 1, k)
        BODY(1, 0, k + 1)
    }
}

extern "C" void kernel_launch(void* const* d_in, const int* in_sizes, int n_in,
                              void* d_out, int out_size) {
    const float* xp = (const float*)d_in[0];
    const float* ap = (const float*)d_in[1];
    float* op = (float*)d_out;

    scan_kernel<<<LG_, TPB_>>>(xp, ap, op);
}

// round 10
// speedup vs baseline: 1.0579x; 1.0579x over previous
#include <cuda_runtime.h>

// h_t = alpha_t * h_{t-1} + x_t over axis 1 of float32 [4, 8192, 1024].
// Persistent design (R6 skeleton): one block per (batch, 32-wide d-tile)
// chain = 128 blocks. Each block scans S=8192 in 32 chunks of 256 steps with
// register double-buffered prefetch. R10: L2 prefetch of chunk k+2 is issued
// AFTER the demand loads of chunk k+1 (and after the aggregate STS), so
// prefetches never delay demand traffic at the burst head; they soak up
// residual DRAM slack during the fold/store section.

#define B_      4
#define S_      8192
#define D_      1024
#define R_      16                    // s-steps per thread per chunk
#define SUBS_   16                    // warps per block
#define TPB_    512
#define DTILE_  32                    // d-lanes per block
#define CHUNK_  (R_ * SUBS_)          // 256 s-steps per chunk
#define ITERS_  (S_ / CHUNK_)         // 32 chunks per chain
#define LG_     (B_ * (D_ / DTILE_))  // 128 chains = 128 blocks

// One chunk body. CUR/NXT are compile-time buffer indices (ping-pong).
// Order: demand-load chunk K+1, local scan of K, STS aggregates,
// L2-prefetch chunk K+2 (fire-and-forget, behind the demand burst),
// barrier, fold, stores.
#define BODY(CUR, NXT, K)                                                     \
    {                                                                         \
        const size_t nbase = base + (size_t)CHUNK_ * D_;                      \
        if ((K) + 1 < ITERS_) {                                               \
            _Pragma("unroll")                                                 \
            for (int r = 0; r < R_; r++)                                      \
                A[NXT][r] = __ldcs(alpha + nbase + (size_t)r * D_);           \
            _Pragma("unroll")                                                 \
            for (int r = 0; r < R_; r++)                                      \
                X[NXT][r] = __ldcs(x + nbase + (size_t)r * D_);               \
        }                                                                     \
        float P = 1.0f, L = 0.0f;                                             \
        _Pragma("unroll")                                                     \
        for (int r = 0; r < R_; r++) {                                        \
            L = fmaf(A[CUR][r], L, X[CUR][r]);                                \
            P = P * A[CUR][r];                                                \
            A[CUR][r] = P;   /* per-step cumprod  */                          \
            X[CUR][r] = L;   /* per-step local scan */                        \
        }                                                                     \
        sp[CUR][w][lane] = P;                                                 \
        sl[CUR][w][lane] = L;                                                 \
        if ((K) + 2 < ITERS_) {                                               \
            /* one prefetch instr per warp: lanes 0-15 cover the 16 A-rows, */\
            /* lanes 16-31 the 16 X-rows of this warp's chunk-(K+2) slab.   */\
            const float* pfa = (lane < 16) ? alpha : x;                       \
            const float* pf  = pfa + (base + (size_t)2 * CHUNK_ * D_          \
                                      + (size_t)(lane & 15) * D_              \
                                      - (size_t)lane);                        \
            asm volatile("prefetch.global.L2 [%0];" :: "l"(pf));              \
        }                                                                     \
        __syncthreads();                                                      \
        /* every warp folds all 16 aggregates: h0 = prefix before own warp, */\
        /* acc = full fold -> next chunk's carry (identical in all warps).  */\
        float acc = cin, h0 = cin;                                            \
        _Pragma("unroll")                                                     \
        for (int w2 = 0; w2 < SUBS_; w2++) {                                  \
            if (w2 == w) h0 = acc;                                            \
            acc = fmaf(sp[CUR][w2][lane], acc, sl[CUR][w2][lane]);            \
        }                                                                     \
        cin = acc;                                                            \
        _Pragma("unroll")                                                     \
        for (int r = 0; r < R_; r++)                                          \
            __stcs(out + base + (size_t)r * D_, fmaf(A[CUR][r], h0, X[CUR][r]));\
        base = nbase;                                                         \
    }

__global__ __launch_bounds__(TPB_, 1) void scan_kernel(const float* __restrict__ x,
                                                       const float* __restrict__ alpha,
                                                       float* __restrict__ out) {
    // Double-buffered per-warp aggregates: one __syncthreads per chunk is
    // race-free (sync at k+1 separates read(k) from write(k+2), same buffer).
    __shared__ float sp[2][SUBS_][DTILE_];
    __shared__ float sl[2][SUBS_][DTILE_];

    const int lane = threadIdx.x & 31;
    const int w    = threadIdx.x >> 5;    // warp = s-subchunk within chunk
    const int lg   = blockIdx.x;          // chain: b * 32 + dtile
    const int b    = lg >> 5;
    const int dt   = lg & 31;
    const int d    = dt * DTILE_ + lane;

    size_t base = ((size_t)b * S_ + (size_t)w * R_) * (size_t)D_ + d;

    float A[2][R_], X[2][R_];
    float cin = 0.0f;

    // Preload chunk 0 (demand), then prefetch chunk 1 lines behind it.
#pragma unroll
    for (int r = 0; r < R_; r++) A[0][r] = __ldcs(alpha + base + (size_t)r * D_);
#pragma unroll
    for (int r = 0; r < R_; r++) X[0][r] = __ldcs(x + base + (size_t)r * D_);
    {
        const float* pfa = (lane < 16) ? alpha : x;
        const float* pf  = pfa + (base + (size_t)CHUNK_ * D_
                                  + (size_t)(lane & 15) * D_ - (size_t)lane);
        asm volatile("prefetch.global.L2 [%0];" :: "l"(pf));
    }

#pragma unroll 1
    for (int k = 0; k < ITERS_; k += 2) {
        BODY(0, 1, k)
        BODY(1, 0, k + 1)
    }
}

extern "C" void kernel_launch(void* const* d_in, const int* in_sizes, int n_in,
                              void* d_out, int out_size) {
    const float* xp = (const float*)d_in[0];
    const float* ap = (const float*)d_in[1];
    float* op = (float*)d_out;

    scan_kernel<<<LG_, TPB_>>>(xp, ap, op);
}